// round 1
// baseline (speedup 1.0000x reference)
#include <cuda_runtime.h>
#include <math.h>

// Problem constants
#define B_     8
#define L_     8192
#define C_     512
#define H_     8
#define WS_    32
#define SHIFT_ 16
#define MLP_   2048
#define D_     64               // C/H
#define NW_    256              // windows per batch (L/WS)
#define NTOK   (B_*L_)          // 65536 tokens
#define NWIN   (B_*NW_)         // 2048 windows

// -------------------- scratch (static device globals; no allocation) ------
__device__ float g_h  [(size_t)NTOK * C_];        // LN1(+roll) output; reused: proj, then h2
__device__ float g_qkv[(size_t)NTOK * 3 * C_];    // qkv
__device__ float g_o  [(size_t)NTOK * C_];        // attention output (window layout == token layout)
__device__ float g_y  [(size_t)NTOK * C_];        // residual y
__device__ float g_mlp[(size_t)NTOK * MLP_];      // fc1/gelu activations

// ==========================================================================
// LayerNorm with optional circular roll of the *source* index:
//   out[b,l,:] = LN(in[b, (l+shift) mod L, :]) * gamma + beta
// 128 threads / token, float4 per thread (C=512).
// ==========================================================================
__global__ void ln_roll_kernel(const float* __restrict__ in,
                               const float* __restrict__ gamma,
                               const float* __restrict__ beta,
                               float* __restrict__ out, int shift)
{
    int t   = blockIdx.x;
    int b   = t >> 13;              // L = 8192 = 2^13
    int l   = t & (L_ - 1);
    int src = (b << 13) | ((l + shift) & (L_ - 1));
    int tid = threadIdx.x;          // 0..127

    float4 v = ((const float4*)(in + (size_t)src * C_))[tid];
    float s = v.x + v.y + v.z + v.w;
    float q = v.x*v.x + v.y*v.y + v.z*v.z + v.w*v.w;

    #pragma unroll
    for (int o = 16; o > 0; o >>= 1) {
        s += __shfl_xor_sync(0xffffffffu, s, o);
        q += __shfl_xor_sync(0xffffffffu, q, o);
    }
    __shared__ float ss[4], sq[4];
    int w = tid >> 5;
    if ((tid & 31) == 0) { ss[w] = s; sq[w] = q; }
    __syncthreads();
    s = ss[0] + ss[1] + ss[2] + ss[3];
    q = sq[0] + sq[1] + sq[2] + sq[3];

    float mean = s * (1.0f / C_);
    float var  = q * (1.0f / C_) - mean * mean;
    float inv  = rsqrtf(var + 1e-5f);

    float4 g4 = ((const float4*)gamma)[tid];
    float4 b4 = ((const float4*)beta)[tid];
    float4 r;
    r.x = (v.x - mean) * inv * g4.x + b4.x;
    r.y = (v.y - mean) * inv * g4.y + b4.y;
    r.z = (v.z - mean) * inv * g4.z + b4.z;
    r.w = (v.w - mean) * inv * g4.w + b4.w;
    ((float4*)(out + (size_t)t * C_))[tid] = r;
}

// ==========================================================================
// y[b,l,:] = x[b,l,:] + p[b, (l-SHIFT) mod L, :]    (roll(+SHIFT) + residual)
// ==========================================================================
__global__ void roll_add_kernel(const float* __restrict__ x,
                                const float* __restrict__ p,
                                float* __restrict__ y)
{
    int t   = blockIdx.x;
    int b   = t >> 13;
    int l   = t & (L_ - 1);
    int src = (b << 13) | ((l - SHIFT_) & (L_ - 1));
    int tid = threadIdx.x; // 0..127

    float4 a = ((const float4*)(x + (size_t)t   * C_))[tid];
    float4 c = ((const float4*)(p + (size_t)src * C_))[tid];
    a.x += c.x; a.y += c.y; a.z += c.z; a.w += c.w;
    ((float4*)(y + (size_t)t * C_))[tid] = a;
}

// ==========================================================================
// SGEMM: O[N,M] = A[N,K] @ W[M,K]^T  (+bias) (+epilogue)
//   EPI 0: plain (+bias if non-null)
//   EPI 1: exact GELU(acc+bias)
//   EPI 2: acc + bias + res[row,col]   (final residual add)
// 128x128 tile, BK=8, 256 threads, 8x8 per thread. All dims divide evenly.
// ==========================================================================
#define BM 128
#define BN 128
#define BK 8

template<int EPI>
__global__ __launch_bounds__(256)
void gemm_kernel(const float* __restrict__ A, const float* __restrict__ W,
                 const float* __restrict__ bias, const float* __restrict__ res,
                 float* __restrict__ O, int K, int M)
{
    __shared__ float As[BK][BM];
    __shared__ float Bs[BK][BN];

    int tid = threadIdx.x;
    int tx  = tid & 15;         // 0..15 -> output col group
    int ty  = tid >> 4;         // 0..15 -> output row group
    int rowBase = blockIdx.y * BM;
    int colBase = blockIdx.x * BN;

    const float* Ap = A + (size_t)rowBase * K;
    const float* Wp = W + (size_t)colBase * K;

    int lrow = tid >> 1;        // 0..127
    int lk   = (tid & 1) * 4;   // 0 or 4

    float acc[8][8];
    #pragma unroll
    for (int i = 0; i < 8; i++)
        #pragma unroll
        for (int j = 0; j < 8; j++) acc[i][j] = 0.0f;

    for (int k0 = 0; k0 < K; k0 += BK) {
        float4 a = *(const float4*)(Ap + (size_t)lrow * K + k0 + lk);
        float4 w = *(const float4*)(Wp + (size_t)lrow * K + k0 + lk);
        As[lk+0][lrow] = a.x; As[lk+1][lrow] = a.y;
        As[lk+2][lrow] = a.z; As[lk+3][lrow] = a.w;
        Bs[lk+0][lrow] = w.x; Bs[lk+1][lrow] = w.y;
        Bs[lk+2][lrow] = w.z; Bs[lk+3][lrow] = w.w;
        __syncthreads();

        #pragma unroll
        for (int kk = 0; kk < BK; kk++) {
            float4 a0 = *(const float4*)&As[kk][ty*8];
            float4 a1 = *(const float4*)&As[kk][ty*8+4];
            float4 b0 = *(const float4*)&Bs[kk][tx*8];
            float4 b1 = *(const float4*)&Bs[kk][tx*8+4];
            float ar[8] = {a0.x,a0.y,a0.z,a0.w,a1.x,a1.y,a1.z,a1.w};
            float br[8] = {b0.x,b0.y,b0.z,b0.w,b1.x,b1.y,b1.z,b1.w};
            #pragma unroll
            for (int i = 0; i < 8; i++)
                #pragma unroll
                for (int j = 0; j < 8; j++)
                    acc[i][j] = fmaf(ar[i], br[j], acc[i][j]);
        }
        __syncthreads();
    }

    #pragma unroll
    for (int i = 0; i < 8; i++) {
        int gr = rowBase + ty*8 + i;
        #pragma unroll
        for (int j = 0; j < 8; j++) {
            int gc = colBase + tx*8 + j;
            float v = acc[i][j];
            if (bias) v += bias[gc];
            if (EPI == 1) {
                v = 0.5f * v * (1.0f + erff(v * 0.70710678118654752440f));
            } else if (EPI == 2) {
                v += res[(size_t)gr * M + gc];
            }
            O[(size_t)gr * M + gc] = v;
        }
    }
}

// ==========================================================================
// Windowed attention, one block per (window, head). 256 threads.
//   S = softmax(q k^T * scale); S += rel_bias + shift_mask; S = softmax(S);
//   O = S @ v    (faithful double-softmax per reference)
// qkv layout per token row: [q(512) | k(512) | v(512)], head h at cols h*64.
// ==========================================================================
__global__ __launch_bounds__(256)
void attn_kernel(const float* __restrict__ qkv, const float* __restrict__ relt,
                 float* __restrict__ out)
{
    int win = blockIdx.x;           // 0..2047 (= b*nW + wi)
    int h   = blockIdx.y;           // 0..7
    int wi  = win & (NW_ - 1);
    int tid = threadIdx.x;

    __shared__ float qs[WS_*D_], ks[WS_*D_], vs[WS_*D_];
    __shared__ float s[WS_][WS_+1];

    // load q,k,v tiles (32x64 each)
    const float* base = qkv + (size_t)(win * WS_) * (3*C_) + h*D_;
    #pragma unroll
    for (int it = 0; it < 2; it++) {
        int i = tid + it*256;           // 0..511 float4 index
        int r = i >> 4;                 // row 0..31 (16 float4 per row)
        int c = (i & 15) * 4;
        const float* rp = base + (size_t)r * (3*C_);
        *(float4*)&qs[r*D_+c] = *(const float4*)(rp + c);
        *(float4*)&ks[r*D_+c] = *(const float4*)(rp + C_  + c);
        *(float4*)&vs[r*D_+c] = *(const float4*)(rp + 2*C_ + c);
    }
    __syncthreads();

    // scores: 4 elements per thread (same row x, 4 consecutive cols)
    {
        int x  = tid >> 3;
        int y0 = (tid & 7) * 4;
        float a0 = 0.f, a1 = 0.f, a2 = 0.f, a3 = 0.f;
        const float* qp = &qs[x*D_];
        #pragma unroll 8
        for (int kk = 0; kk < D_; kk++) {
            float qv = qp[kk];
            a0 = fmaf(qv, ks[(y0+0)*D_+kk], a0);
            a1 = fmaf(qv, ks[(y0+1)*D_+kk], a1);
            a2 = fmaf(qv, ks[(y0+2)*D_+kk], a2);
            a3 = fmaf(qv, ks[(y0+3)*D_+kk], a3);
        }
        const float scale = 0.125f;     // d^-0.5, d=64
        s[x][y0+0] = a0*scale; s[x][y0+1] = a1*scale;
        s[x][y0+2] = a2*scale; s[x][y0+3] = a3*scale;
    }
    __syncthreads();

    // per-row: softmax -> +bias+mask -> softmax. 8 warps x 4 rows.
    {
        int warp = tid >> 5, lane = tid & 31;
        bool lastw = (wi == NW_ - 1);
        #pragma unroll
        for (int rr = 0; rr < 4; rr++) {
            int r = warp*4 + rr;
            float v = s[r][lane];
            float mx = v;
            #pragma unroll
            for (int o = 16; o > 0; o >>= 1) mx = fmaxf(mx, __shfl_xor_sync(0xffffffffu, mx, o));
            float e = expf(v - mx);
            float sm = e;
            #pragma unroll
            for (int o = 16; o > 0; o >>= 1) sm += __shfl_xor_sync(0xffffffffu, sm, o);
            v = e / sm;
            // relative position bias + shift mask
            float bm = relt[(r - lane + WS_ - 1) * H_ + h];
            if (lastw && ((r < SHIFT_) != (lane < SHIFT_))) bm -= 100.0f;
            v += bm;
            // second softmax
            mx = v;
            #pragma unroll
            for (int o = 16; o > 0; o >>= 1) mx = fmaxf(mx, __shfl_xor_sync(0xffffffffu, mx, o));
            e = expf(v - mx);
            sm = e;
            #pragma unroll
            for (int o = 16; o > 0; o >>= 1) sm += __shfl_xor_sync(0xffffffffu, sm, o);
            s[r][lane] = e / sm;
        }
    }
    __syncthreads();

    // O = S @ V : 8 output elements per thread (row x, 8 consecutive d cols)
    {
        int x  = tid >> 3;
        int j0 = (tid & 7) * 8;
        float acc[8] = {0.f,0.f,0.f,0.f,0.f,0.f,0.f,0.f};
        #pragma unroll
        for (int y = 0; y < WS_; y++) {
            float sv = s[x][y];
            const float* vp = &vs[y*D_ + j0];
            #pragma unroll
            for (int jj = 0; jj < 8; jj++)
                acc[jj] = fmaf(sv, vp[jj], acc[jj]);
        }
        float* op = out + (size_t)(win*WS_ + x) * C_ + h*D_ + j0;
        *(float4*)(op)   = make_float4(acc[0], acc[1], acc[2], acc[3]);
        *(float4*)(op+4) = make_float4(acc[4], acc[5], acc[6], acc[7]);
    }
}

// ==========================================================================
extern "C" void kernel_launch(void* const* d_in, const int* in_sizes, int n_in,
                              void* d_out, int out_size)
{
    const float* x      = (const float*)d_in[0];
    const float* w_qkv  = (const float*)d_in[1];
    const float* w_out  = (const float*)d_in[2];
    const float* b_out  = (const float*)d_in[3];
    const float* relt   = (const float*)d_in[4];
    const float* g1     = (const float*)d_in[5];
    const float* be1    = (const float*)d_in[6];
    const float* g2     = (const float*)d_in[7];
    const float* be2    = (const float*)d_in[8];
    const float* w_fc1  = (const float*)d_in[9];
    const float* b_fc1  = (const float*)d_in[10];
    const float* w_fc2  = (const float*)d_in[11];
    const float* b_fc2  = (const float*)d_in[12];
    float* out = (float*)d_out;

    float *hbuf, *qkvb, *obuf, *ybuf, *mlpb;
    cudaGetSymbolAddress((void**)&hbuf, g_h);
    cudaGetSymbolAddress((void**)&qkvb, g_qkv);
    cudaGetSymbolAddress((void**)&obuf, g_o);
    cudaGetSymbolAddress((void**)&ybuf, g_y);
    cudaGetSymbolAddress((void**)&mlpb, g_mlp);

    // 1) h = roll(LN1(x), -SHIFT)
    ln_roll_kernel<<<NTOK, 128>>>(x, g1, be1, hbuf, SHIFT_);

    // 2) qkv = h @ w_qkv^T
    gemm_kernel<0><<<dim3(3*C_/BN, NTOK/BM), 256>>>(hbuf, w_qkv, nullptr, nullptr,
                                                    qkvb, C_, 3*C_);

    // 3) windowed attention -> obuf (window layout == shifted token layout)
    attn_kernel<<<dim3(NWIN, H_), 256>>>(qkvb, relt, obuf);

    // 4) proj = obuf @ w_out^T + b_out   (into hbuf, now free)
    gemm_kernel<0><<<dim3(C_/BN, NTOK/BM), 256>>>(obuf, w_out, b_out, nullptr,
                                                  hbuf, C_, C_);

    // 5) y = x + roll(proj, +SHIFT)
    roll_add_kernel<<<NTOK, 128>>>(x, hbuf, ybuf);

    // 6) h2 = LN2(y)  (into hbuf)
    ln_roll_kernel<<<NTOK, 128>>>(ybuf, g2, be2, hbuf, 0);

    // 7) mlp = gelu(h2 @ w_fc1^T + b_fc1)
    gemm_kernel<1><<<dim3(MLP_/BN, NTOK/BM), 256>>>(hbuf, w_fc1, b_fc1, nullptr,
                                                    mlpb, C_, MLP_);

    // 8) out = y + mlp @ w_fc2^T + b_fc2
    gemm_kernel<2><<<dim3(C_/BN, NTOK/BM), 256>>>(mlpb, w_fc2, b_fc2, ybuf,
                                                  out, MLP_, C_);
}

// round 3
// speedup vs baseline: 2.7859x; 2.7859x over previous
#include <cuda_runtime.h>
#include <math.h>
#include <stdint.h>

// Problem constants
#define B_     8
#define L_     8192
#define C_     512
#define H_     8
#define WS_    32
#define SHIFT_ 16
#define MLP_   2048
#define D_     64
#define NW_    256
#define NTOK   (B_*L_)          // 65536
#define NWIN   (B_*NW_)         // 2048

// GEMM tiling (tf32 mma.sync path)
#define BM 128
#define BN 128
#define BK 32
#define ASTR 36                  // smem row stride in floats (conflict-free frag LDS)
#define STAGE_F (BM*ASTR)        // floats per stage per matrix = 4608
#define SMEM_BYTES (2*2*STAGE_F*4)   // A+B, 2 stages = 73728

// -------------------- scratch -------------------------------------------
__device__ float g_h  [(size_t)NTOK * C_];
__device__ float g_qkv[(size_t)NTOK * 3 * C_];
__device__ float g_o  [(size_t)NTOK * C_];
__device__ float g_y  [(size_t)NTOK * C_];
__device__ float g_mlp[(size_t)NTOK * MLP_];

// -------------------- helpers -------------------------------------------
__device__ __forceinline__ uint32_t smem_u32(const void* p) {
    uint32_t a;
    asm("{ .reg .u64 t; cvta.to.shared.u64 t, %1; cvt.u32.u64 %0, t; }" : "=r"(a) : "l"(p));
    return a;
}
__device__ __forceinline__ void cp_async16(uint32_t dst, const void* src) {
    asm volatile("cp.async.cg.shared.global [%0], [%1], 16;" :: "r"(dst), "l"(src));
}
__device__ __forceinline__ uint32_t f2tf32(float x) {
    uint32_t u;
    asm("cvt.rna.tf32.f32 %0, %1;" : "=r"(u) : "f"(x));
    return u;
}
__device__ __forceinline__ void mma_tf32(float& d0, float& d1, float& d2, float& d3,
                                         uint32_t a0, uint32_t a1, uint32_t a2, uint32_t a3,
                                         uint32_t b0, uint32_t b1) {
    asm volatile(
        "mma.sync.aligned.m16n8k8.row.col.f32.tf32.tf32.f32 "
        "{%0,%1,%2,%3}, {%4,%5,%6,%7}, {%8,%9}, {%0,%1,%2,%3};"
        : "+f"(d0), "+f"(d1), "+f"(d2), "+f"(d3)
        : "r"(a0), "r"(a1), "r"(a2), "r"(a3), "r"(b0), "r"(b1));
}

// ==========================================================================
// tf32 tensor-core GEMM: O[N,M] = A[N,K] @ W[M,K]^T (+bias)(+epilogue)
//   EPI 0: +bias if non-null; EPI 1: exact GELU(acc+bias); EPI 2: +bias+res
// 256 threads = 8 warps (2x4), warp tile 64x32, block tile 128x128, BK=32.
// ==========================================================================
template<int EPI>
__global__ __launch_bounds__(256)
void tc_gemm(const float* __restrict__ A, const float* __restrict__ W,
             const float* __restrict__ bias, const float* __restrict__ res,
             float* __restrict__ O, int K, int M)
{
    extern __shared__ float smem[];
    float* As = smem;                    // [2][128][36]
    float* Bs = smem + 2*STAGE_F;        // [2][128][36]
    const uint32_t asb = smem_u32(As);
    const uint32_t bsb = smem_u32(Bs);

    const int tid  = threadIdx.x;
    const int wid  = tid >> 5;
    const int lane = tid & 31;
    const int wm   = wid >> 2;           // 0..1
    const int wn   = wid & 3;            // 0..3
    const int rowBase = blockIdx.y * BM;
    const int colBase = blockIdx.x * BN;

    const float* Ag = A + (size_t)rowBase * K;
    const float* Wg = W + (size_t)colBase * K;

    const int nIter = K >> 5;            // K / 32

    // global->smem stage load: 4 x 16B chunks per thread per matrix
    auto load_stage = [&](int it) {
        int buf = it & 1;
        int k0  = it * BK;
        uint32_t aB = asb + buf * STAGE_F * 4;
        uint32_t bB = bsb + buf * STAGE_F * 4;
        #pragma unroll
        for (int t = 0; t < 4; t++) {
            int idx = tid + t * 256;     // 0..1023
            int row = idx >> 3;          // 0..127
            int c16 = idx & 7;           // 0..7 (16B chunks across 32 floats)
            uint32_t off = row * (ASTR*4) + c16 * 16;
            cp_async16(aB + off, Ag + (size_t)row * K + k0 + c16 * 4);
            cp_async16(bB + off, Wg + (size_t)row * K + k0 + c16 * 4);
        }
        asm volatile("cp.async.commit_group;" ::: "memory");
    };

    float acc[4][4][4];
    #pragma unroll
    for (int mi = 0; mi < 4; mi++)
        #pragma unroll
        for (int ni = 0; ni < 4; ni++)
            #pragma unroll
            for (int r = 0; r < 4; r++) acc[mi][ni][r] = 0.0f;

    load_stage(0);

    const int lr = lane >> 2;            // 0..7
    const int lc = lane & 3;             // 0..3

    for (int it = 0; it < nIter; it++) {
        if (it + 1 < nIter) load_stage(it + 1);
        if (it + 1 < nIter)
            asm volatile("cp.async.wait_group 1;" ::: "memory");
        else
            asm volatile("cp.async.wait_group 0;" ::: "memory");
        __syncthreads();

        const float* Ab = As + (it & 1) * STAGE_F;
        const float* Bb = Bs + (it & 1) * STAGE_F;

        #pragma unroll
        for (int kk = 0; kk < BK; kk += 8) {
            uint32_t af[4][4], bf[4][2];
            #pragma unroll
            for (int mi = 0; mi < 4; mi++) {
                const float* p = Ab + (wm*64 + mi*16 + lr) * ASTR + kk + lc;
                af[mi][0] = f2tf32(p[0]);
                af[mi][1] = f2tf32(p[8*ASTR]);
                af[mi][2] = f2tf32(p[4]);
                af[mi][3] = f2tf32(p[8*ASTR + 4]);
            }
            #pragma unroll
            for (int ni = 0; ni < 4; ni++) {
                const float* p = Bb + (wn*32 + ni*8 + lr) * ASTR + kk + lc;
                bf[ni][0] = f2tf32(p[0]);
                bf[ni][1] = f2tf32(p[4]);
            }
            #pragma unroll
            for (int mi = 0; mi < 4; mi++)
                #pragma unroll
                for (int ni = 0; ni < 4; ni++)
                    mma_tf32(acc[mi][ni][0], acc[mi][ni][1], acc[mi][ni][2], acc[mi][ni][3],
                             af[mi][0], af[mi][1], af[mi][2], af[mi][3],
                             bf[ni][0], bf[ni][1]);
        }
        __syncthreads();
    }

    // epilogue: c0,c1 at (row, col..col+1); c2,c3 at (row+8, col..col+1)
    #pragma unroll
    for (int mi = 0; mi < 4; mi++) {
        int r0 = rowBase + wm*64 + mi*16 + lr;
        #pragma unroll
        for (int ni = 0; ni < 4; ni++) {
            int c0 = colBase + wn*32 + ni*8 + lc*2;
            float b0 = 0.f, b1 = 0.f;
            if (bias) { b0 = bias[c0]; b1 = bias[c0+1]; }
            #pragma unroll
            for (int half = 0; half < 2; half++) {
                int gr = r0 + half*8;
                float v0 = acc[mi][ni][half*2+0] + b0;
                float v1 = acc[mi][ni][half*2+1] + b1;
                if (EPI == 1) {
                    v0 = 0.5f * v0 * (1.0f + erff(v0 * 0.70710678118654752440f));
                    v1 = 0.5f * v1 * (1.0f + erff(v1 * 0.70710678118654752440f));
                } else if (EPI == 2) {
                    const float2 rr = *(const float2*)(res + (size_t)gr * M + c0);
                    v0 += rr.x; v1 += rr.y;
                }
                *(float2*)(O + (size_t)gr * M + c0) = make_float2(v0, v1);
            }
        }
    }
}

// ==========================================================================
// LayerNorm (+optional source roll)
// ==========================================================================
__global__ void ln_roll_kernel(const float* __restrict__ in,
                               const float* __restrict__ gamma,
                               const float* __restrict__ beta,
                               float* __restrict__ out, int shift)
{
    int t   = blockIdx.x;
    int b   = t >> 13;
    int l   = t & (L_ - 1);
    int src = (b << 13) | ((l + shift) & (L_ - 1));
    int tid = threadIdx.x;

    float4 v = ((const float4*)(in + (size_t)src * C_))[tid];
    float s = v.x + v.y + v.z + v.w;
    float q = v.x*v.x + v.y*v.y + v.z*v.z + v.w*v.w;
    #pragma unroll
    for (int o = 16; o > 0; o >>= 1) {
        s += __shfl_xor_sync(0xffffffffu, s, o);
        q += __shfl_xor_sync(0xffffffffu, q, o);
    }
    __shared__ float ss[4], sq[4];
    int w = tid >> 5;
    if ((tid & 31) == 0) { ss[w] = s; sq[w] = q; }
    __syncthreads();
    s = ss[0] + ss[1] + ss[2] + ss[3];
    q = sq[0] + sq[1] + sq[2] + sq[3];

    float mean = s * (1.0f / C_);
    float var  = q * (1.0f / C_) - mean * mean;
    float inv  = rsqrtf(var + 1e-5f);

    float4 g4 = ((const float4*)gamma)[tid];
    float4 b4 = ((const float4*)beta)[tid];
    float4 r;
    r.x = (v.x - mean) * inv * g4.x + b4.x;
    r.y = (v.y - mean) * inv * g4.y + b4.y;
    r.z = (v.z - mean) * inv * g4.z + b4.z;
    r.w = (v.w - mean) * inv * g4.w + b4.w;
    ((float4*)(out + (size_t)t * C_))[tid] = r;
}

__global__ void roll_add_kernel(const float* __restrict__ x,
                                const float* __restrict__ p,
                                float* __restrict__ y)
{
    int t   = blockIdx.x;
    int b   = t >> 13;
    int l   = t & (L_ - 1);
    int src = (b << 13) | ((l - SHIFT_) & (L_ - 1));
    int tid = threadIdx.x;
    float4 a = ((const float4*)(x + (size_t)t   * C_))[tid];
    float4 c = ((const float4*)(p + (size_t)src * C_))[tid];
    a.x += c.x; a.y += c.y; a.z += c.z; a.w += c.w;
    ((float4*)(y + (size_t)t * C_))[tid] = a;
}

// ==========================================================================
// Windowed attention (double softmax, faithful to reference)
// ==========================================================================
__global__ __launch_bounds__(256)
void attn_kernel(const float* __restrict__ qkv, const float* __restrict__ relt,
                 float* __restrict__ out)
{
    int win = blockIdx.x;
    int h   = blockIdx.y;
    int wi  = win & (NW_ - 1);
    int tid = threadIdx.x;

    __shared__ float qs[WS_*D_], ks[WS_*D_], vs[WS_*D_];
    __shared__ float s[WS_][WS_+1];

    const float* base = qkv + (size_t)(win * WS_) * (3*C_) + h*D_;
    #pragma unroll
    for (int it = 0; it < 2; it++) {
        int i = tid + it*256;
        int r = i >> 4;
        int c = (i & 15) * 4;
        const float* rp = base + (size_t)r * (3*C_);
        *(float4*)&qs[r*D_+c] = *(const float4*)(rp + c);
        *(float4*)&ks[r*D_+c] = *(const float4*)(rp + C_  + c);
        *(float4*)&vs[r*D_+c] = *(const float4*)(rp + 2*C_ + c);
    }
    __syncthreads();

    {
        int x  = tid >> 3;
        int y0 = (tid & 7) * 4;
        float a0 = 0.f, a1 = 0.f, a2 = 0.f, a3 = 0.f;
        const float* qp = &qs[x*D_];
        #pragma unroll 8
        for (int kk = 0; kk < D_; kk++) {
            float qv = qp[kk];
            a0 = fmaf(qv, ks[(y0+0)*D_+kk], a0);
            a1 = fmaf(qv, ks[(y0+1)*D_+kk], a1);
            a2 = fmaf(qv, ks[(y0+2)*D_+kk], a2);
            a3 = fmaf(qv, ks[(y0+3)*D_+kk], a3);
        }
        const float scale = 0.125f;
        s[x][y0+0] = a0*scale; s[x][y0+1] = a1*scale;
        s[x][y0+2] = a2*scale; s[x][y0+3] = a3*scale;
    }
    __syncthreads();

    {
        int warp = tid >> 5, lane = tid & 31;
        bool lastw = (wi == NW_ - 1);
        #pragma unroll
        for (int rr = 0; rr < 4; rr++) {
            int r = warp*4 + rr;
            float v = s[r][lane];
            float mx = v;
            #pragma unroll
            for (int o = 16; o > 0; o >>= 1) mx = fmaxf(mx, __shfl_xor_sync(0xffffffffu, mx, o));
            float e = expf(v - mx);
            float sm = e;
            #pragma unroll
            for (int o = 16; o > 0; o >>= 1) sm += __shfl_xor_sync(0xffffffffu, sm, o);
            v = e / sm;
            float bm = relt[(r - lane + WS_ - 1) * H_ + h];
            if (lastw && ((r < SHIFT_) != (lane < SHIFT_))) bm -= 100.0f;
            v += bm;
            mx = v;
            #pragma unroll
            for (int o = 16; o > 0; o >>= 1) mx = fmaxf(mx, __shfl_xor_sync(0xffffffffu, mx, o));
            e = expf(v - mx);
            sm = e;
            #pragma unroll
            for (int o = 16; o > 0; o >>= 1) sm += __shfl_xor_sync(0xffffffffu, sm, o);
            s[r][lane] = e / sm;
        }
    }
    __syncthreads();

    {
        int x  = tid >> 3;
        int j0 = (tid & 7) * 8;
        float acc[8] = {0.f,0.f,0.f,0.f,0.f,0.f,0.f,0.f};
        #pragma unroll
        for (int y = 0; y < WS_; y++) {
            float sv = s[x][y];
            const float* vp = &vs[y*D_ + j0];
            #pragma unroll
            for (int jj = 0; jj < 8; jj++)
                acc[jj] = fmaf(sv, vp[jj], acc[jj]);
        }
        float* op = out + (size_t)(win*WS_ + x) * C_ + h*D_ + j0;
        *(float4*)(op)   = make_float4(acc[0], acc[1], acc[2], acc[3]);
        *(float4*)(op+4) = make_float4(acc[4], acc[5], acc[6], acc[7]);
    }
}

// ==========================================================================
extern "C" void kernel_launch(void* const* d_in, const int* in_sizes, int n_in,
                              void* d_out, int out_size)
{
    const float* x      = (const float*)d_in[0];
    const float* w_qkv  = (const float*)d_in[1];
    const float* w_out  = (const float*)d_in[2];
    const float* b_out  = (const float*)d_in[3];
    const float* relt   = (const float*)d_in[4];
    const float* g1     = (const float*)d_in[5];
    const float* be1    = (const float*)d_in[6];
    const float* g2     = (const float*)d_in[7];
    const float* be2    = (const float*)d_in[8];
    const float* w_fc1  = (const float*)d_in[9];
    const float* b_fc1  = (const float*)d_in[10];
    const float* w_fc2  = (const float*)d_in[11];
    const float* b_fc2  = (const float*)d_in[12];
    float* out = (float*)d_out;

    float *hbuf, *qkvb, *obuf, *ybuf, *mlpb;
    cudaGetSymbolAddress((void**)&hbuf, g_h);
    cudaGetSymbolAddress((void**)&qkvb, g_qkv);
    cudaGetSymbolAddress((void**)&obuf, g_o);
    cudaGetSymbolAddress((void**)&ybuf, g_y);
    cudaGetSymbolAddress((void**)&mlpb, g_mlp);

    cudaFuncSetAttribute(tc_gemm<0>, cudaFuncAttributeMaxDynamicSharedMemorySize, SMEM_BYTES);
    cudaFuncSetAttribute(tc_gemm<1>, cudaFuncAttributeMaxDynamicSharedMemorySize, SMEM_BYTES);
    cudaFuncSetAttribute(tc_gemm<2>, cudaFuncAttributeMaxDynamicSharedMemorySize, SMEM_BYTES);

    // 1) h = roll(LN1(x), -SHIFT)
    ln_roll_kernel<<<NTOK, 128>>>(x, g1, be1, hbuf, SHIFT_);

    // 2) qkv = h @ w_qkv^T
    tc_gemm<0><<<dim3(3*C_/BN, NTOK/BM), 256, SMEM_BYTES>>>(hbuf, w_qkv, nullptr, nullptr,
                                                            qkvb, C_, 3*C_);

    // 3) windowed attention
    attn_kernel<<<dim3(NWIN, H_), 256>>>(qkvb, relt, obuf);

    // 4) proj = obuf @ w_out^T + b_out
    tc_gemm<0><<<dim3(C_/BN, NTOK/BM), 256, SMEM_BYTES>>>(obuf, w_out, b_out, nullptr,
                                                          hbuf, C_, C_);

    // 5) y = x + roll(proj, +SHIFT)
    roll_add_kernel<<<NTOK, 128>>>(x, hbuf, ybuf);

    // 6) h2 = LN2(y)
    ln_roll_kernel<<<NTOK, 128>>>(ybuf, g2, be2, hbuf, 0);

    // 7) mlp = gelu(h2 @ w_fc1^T + b_fc1)
    tc_gemm<1><<<dim3(MLP_/BN, NTOK/BM), 256, SMEM_BYTES>>>(hbuf, w_fc1, b_fc1, nullptr,
                                                            mlpb, C_, MLP_);

    // 8) out = y + mlp @ w_fc2^T + b_fc2
    tc_gemm<2><<<dim3(C_/BN, NTOK/BM), 256, SMEM_BYTES>>>(mlpb, w_fc2, b_fc2, ybuf,
                                                          out, MLP_, C_);
}

// round 4
// speedup vs baseline: 2.9405x; 1.0555x over previous
#include <cuda_runtime.h>
#include <math.h>
#include <stdint.h>

// Problem constants
#define B_     8
#define L_     8192
#define C_     512
#define H_     8
#define WS_    32
#define SHIFT_ 16
#define MLP_   2048
#define D_     64
#define NW_    256
#define NTOK   (B_*L_)          // 65536
#define NWIN   (B_*NW_)         // 2048

// GEMM tiling (tf32 mma.sync path)
#define BM 128
#define BN 128
#define BK 32
#define ASTR 36                  // smem row stride in floats (conflict-free frag LDS)
#define STAGE_F (BM*ASTR)        // floats per stage per matrix = 4608
#define SMEM_BYTES (2*2*STAGE_F*4)   // A+B, 2 stages = 73728

// -------------------- scratch -------------------------------------------
__device__ float g_h  [(size_t)NTOK * C_];
__device__ float g_qkv[(size_t)NTOK * 3 * C_];
__device__ float g_o  [(size_t)NTOK * C_];
__device__ float g_y  [(size_t)NTOK * C_];
__device__ float g_mlp[(size_t)NTOK * MLP_];
// rounded weights: w_qkv(786432) | w_out(262144) | w_fc1(1048576) | w_fc2(1048576)
__device__ float g_wr [3145728];
#define WR_QKV 0
#define WR_OUT 786432
#define WR_FC1 (786432 + 262144)
#define WR_FC2 (786432 + 262144 + 1048576)

// -------------------- helpers -------------------------------------------
__device__ __forceinline__ uint32_t smem_u32(const void* p) {
    uint32_t a;
    asm("{ .reg .u64 t; cvta.to.shared.u64 t, %1; cvt.u32.u64 %0, t; }" : "=r"(a) : "l"(p));
    return a;
}
__device__ __forceinline__ void cp_async16(uint32_t dst, const void* src) {
    asm volatile("cp.async.cg.shared.global [%0], [%1], 16;" :: "r"(dst), "l"(src));
}
__device__ __forceinline__ float tf32r(float x) {
    uint32_t u;
    asm("cvt.rna.tf32.f32 %0, %1;" : "=r"(u) : "f"(x));
    return __uint_as_float(u);
}
__device__ __forceinline__ void mma_tf32(float& d0, float& d1, float& d2, float& d3,
                                         uint32_t a0, uint32_t a1, uint32_t a2, uint32_t a3,
                                         uint32_t b0, uint32_t b1) {
    asm volatile(
        "mma.sync.aligned.m16n8k8.row.col.f32.tf32.tf32.f32 "
        "{%0,%1,%2,%3}, {%4,%5,%6,%7}, {%8,%9}, {%0,%1,%2,%3};"
        : "+f"(d0), "+f"(d1), "+f"(d2), "+f"(d3)
        : "r"(a0), "r"(a1), "r"(a2), "r"(a3), "r"(b0), "r"(b1));
}

// round a buffer to tf32 bit pattern (kept in f32 storage)
__global__ void round_tf32_kernel(const float* __restrict__ in, float* __restrict__ out, int n4)
{
    int i = blockIdx.x * 256 + threadIdx.x;
    if (i < n4) {
        float4 v = ((const float4*)in)[i];
        v.x = tf32r(v.x); v.y = tf32r(v.y); v.z = tf32r(v.z); v.w = tf32r(v.w);
        ((float4*)out)[i] = v;
    }
}

// ==========================================================================
// tf32 tensor-core GEMM: O[N,M] = A[N,K] @ W[M,K]^T (+bias)(+epilogue)
//   EPI 0: +bias if non-null
//   EPI 1: tf32round(exact GELU(acc+bias))
//   EPI 2: acc + bias + res[row]      (final out, fp32)
//   EPI 3: write row (l+SHIFT mod L): O[dst] = acc + bias + res[dst]
// Inputs A and W must already be tf32-rounded. No converts in the hot loop.
// 256 threads = 8 warps (2x4), warp tile 64x32, block tile 128x128, BK=32.
// ==========================================================================
template<int EPI>
__global__ __launch_bounds__(256)
void tc_gemm(const float* __restrict__ A, const float* __restrict__ W,
             const float* __restrict__ bias, const float* __restrict__ res,
             float* __restrict__ O, int K, int M)
{
    extern __shared__ float smem[];
    float* As = smem;                    // [2][128][36]
    float* Bs = smem + 2*STAGE_F;        // [2][128][36]
    const uint32_t asb = smem_u32(As);
    const uint32_t bsb = smem_u32(Bs);

    const int tid  = threadIdx.x;
    const int wid  = tid >> 5;
    const int lane = tid & 31;
    const int wm   = wid >> 2;           // 0..1
    const int wn   = wid & 3;            // 0..3
    const int rowBase = blockIdx.y * BM;
    const int colBase = blockIdx.x * BN;

    const float* Ag = A + (size_t)rowBase * K;
    const float* Wg = W + (size_t)colBase * K;

    const int nIter = K >> 5;            // K / 32

    auto load_stage = [&](int it) {
        int buf = it & 1;
        int k0  = it * BK;
        uint32_t aB = asb + buf * STAGE_F * 4;
        uint32_t bB = bsb + buf * STAGE_F * 4;
        #pragma unroll
        for (int t = 0; t < 4; t++) {
            int idx = tid + t * 256;     // 0..1023
            int row = idx >> 3;          // 0..127
            int c16 = idx & 7;           // 0..7
            uint32_t off = row * (ASTR*4) + c16 * 16;
            cp_async16(aB + off, Ag + (size_t)row * K + k0 + c16 * 4);
            cp_async16(bB + off, Wg + (size_t)row * K + k0 + c16 * 4);
        }
        asm volatile("cp.async.commit_group;" ::: "memory");
    };

    float acc[4][4][4];
    #pragma unroll
    for (int mi = 0; mi < 4; mi++)
        #pragma unroll
        for (int ni = 0; ni < 4; ni++)
            #pragma unroll
            for (int r = 0; r < 4; r++) acc[mi][ni][r] = 0.0f;

    load_stage(0);

    const int lr = lane >> 2;            // 0..7
    const int lc = lane & 3;             // 0..3

    for (int it = 0; it < nIter; it++) {
        if (it + 1 < nIter) load_stage(it + 1);
        if (it + 1 < nIter)
            asm volatile("cp.async.wait_group 1;" ::: "memory");
        else
            asm volatile("cp.async.wait_group 0;" ::: "memory");
        __syncthreads();

        const float* Ab = As + (it & 1) * STAGE_F;
        const float* Bb = Bs + (it & 1) * STAGE_F;

        #pragma unroll
        for (int kk = 0; kk < BK; kk += 8) {
            uint32_t af[4][4], bf[4][2];
            #pragma unroll
            for (int mi = 0; mi < 4; mi++) {
                const float* p = Ab + (wm*64 + mi*16 + lr) * ASTR + kk + lc;
                af[mi][0] = __float_as_uint(p[0]);
                af[mi][1] = __float_as_uint(p[8*ASTR]);
                af[mi][2] = __float_as_uint(p[4]);
                af[mi][3] = __float_as_uint(p[8*ASTR + 4]);
            }
            #pragma unroll
            for (int ni = 0; ni < 4; ni++) {
                const float* p = Bb + (wn*32 + ni*8 + lr) * ASTR + kk + lc;
                bf[ni][0] = __float_as_uint(p[0]);
                bf[ni][1] = __float_as_uint(p[4]);
            }
            #pragma unroll
            for (int mi = 0; mi < 4; mi++)
                #pragma unroll
                for (int ni = 0; ni < 4; ni++)
                    mma_tf32(acc[mi][ni][0], acc[mi][ni][1], acc[mi][ni][2], acc[mi][ni][3],
                             af[mi][0], af[mi][1], af[mi][2], af[mi][3],
                             bf[ni][0], bf[ni][1]);
        }
        __syncthreads();
    }

    // epilogue
    #pragma unroll
    for (int mi = 0; mi < 4; mi++) {
        int r0 = rowBase + wm*64 + mi*16 + lr;
        #pragma unroll
        for (int ni = 0; ni < 4; ni++) {
            int c0 = colBase + wn*32 + ni*8 + lc*2;
            float b0 = 0.f, b1 = 0.f;
            if (bias) { b0 = bias[c0]; b1 = bias[c0+1]; }
            #pragma unroll
            for (int half = 0; half < 2; half++) {
                int gr = r0 + half*8;
                float v0 = acc[mi][ni][half*2+0] + b0;
                float v1 = acc[mi][ni][half*2+1] + b1;
                if (EPI == 1) {
                    v0 = tf32r(0.5f * v0 * (1.0f + erff(v0 * 0.70710678118654752440f)));
                    v1 = tf32r(0.5f * v1 * (1.0f + erff(v1 * 0.70710678118654752440f)));
                } else if (EPI == 2) {
                    const float2 rr = *(const float2*)(res + (size_t)gr * M + c0);
                    v0 += rr.x; v1 += rr.y;
                } else if (EPI == 3) {
                    int bb = gr >> 13;
                    int ll = gr & (L_ - 1);
                    gr = (bb << 13) | ((ll + SHIFT_) & (L_ - 1));
                    const float2 rr = *(const float2*)(res + (size_t)gr * M + c0);
                    v0 += rr.x; v1 += rr.y;
                }
                *(float2*)(O + (size_t)gr * M + c0) = make_float2(v0, v1);
            }
        }
    }
}

// ==========================================================================
// LayerNorm (+optional source roll). Output tf32-rounded (feeds GEMM A only).
// ==========================================================================
__global__ void ln_roll_kernel(const float* __restrict__ in,
                               const float* __restrict__ gamma,
                               const float* __restrict__ beta,
                               float* __restrict__ out, int shift)
{
    int t   = blockIdx.x;
    int b   = t >> 13;
    int l   = t & (L_ - 1);
    int src = (b << 13) | ((l + shift) & (L_ - 1));
    int tid = threadIdx.x;

    float4 v = ((const float4*)(in + (size_t)src * C_))[tid];
    float s = v.x + v.y + v.z + v.w;
    float q = v.x*v.x + v.y*v.y + v.z*v.z + v.w*v.w;
    #pragma unroll
    for (int o = 16; o > 0; o >>= 1) {
        s += __shfl_xor_sync(0xffffffffu, s, o);
        q += __shfl_xor_sync(0xffffffffu, q, o);
    }
    __shared__ float ss[4], sq[4];
    int w = tid >> 5;
    if ((tid & 31) == 0) { ss[w] = s; sq[w] = q; }
    __syncthreads();
    s = ss[0] + ss[1] + ss[2] + ss[3];
    q = sq[0] + sq[1] + sq[2] + sq[3];

    float mean = s * (1.0f / C_);
    float var  = q * (1.0f / C_) - mean * mean;
    float inv  = rsqrtf(var + 1e-5f);

    float4 g4 = ((const float4*)gamma)[tid];
    float4 b4 = ((const float4*)beta)[tid];
    float4 r;
    r.x = tf32r((v.x - mean) * inv * g4.x + b4.x);
    r.y = tf32r((v.y - mean) * inv * g4.y + b4.y);
    r.z = tf32r((v.z - mean) * inv * g4.z + b4.z);
    r.w = tf32r((v.w - mean) * inv * g4.w + b4.w);
    ((float4*)(out + (size_t)t * C_))[tid] = r;
}

// ==========================================================================
// Windowed attention (double softmax). Output tf32-rounded (feeds proj GEMM).
// ==========================================================================
__global__ __launch_bounds__(256)
void attn_kernel(const float* __restrict__ qkv, const float* __restrict__ relt,
                 float* __restrict__ out)
{
    int win = blockIdx.x;
    int h   = blockIdx.y;
    int wi  = win & (NW_ - 1);
    int tid = threadIdx.x;

    __shared__ float qs[WS_*D_], ks[WS_*D_], vs[WS_*D_];
    __shared__ float s[WS_][WS_+1];

    const float* base = qkv + (size_t)(win * WS_) * (3*C_) + h*D_;
    #pragma unroll
    for (int it = 0; it < 2; it++) {
        int i = tid + it*256;
        int r = i >> 4;
        int c = (i & 15) * 4;
        const float* rp = base + (size_t)r * (3*C_);
        *(float4*)&qs[r*D_+c] = *(const float4*)(rp + c);
        *(float4*)&ks[r*D_+c] = *(const float4*)(rp + C_  + c);
        *(float4*)&vs[r*D_+c] = *(const float4*)(rp + 2*C_ + c);
    }
    __syncthreads();

    {
        int x  = tid >> 3;
        int y0 = (tid & 7) * 4;
        float a0 = 0.f, a1 = 0.f, a2 = 0.f, a3 = 0.f;
        const float* qp = &qs[x*D_];
        #pragma unroll 8
        for (int kk = 0; kk < D_; kk++) {
            float qv = qp[kk];
            a0 = fmaf(qv, ks[(y0+0)*D_+kk], a0);
            a1 = fmaf(qv, ks[(y0+1)*D_+kk], a1);
            a2 = fmaf(qv, ks[(y0+2)*D_+kk], a2);
            a3 = fmaf(qv, ks[(y0+3)*D_+kk], a3);
        }
        const float scale = 0.125f;
        s[x][y0+0] = a0*scale; s[x][y0+1] = a1*scale;
        s[x][y0+2] = a2*scale; s[x][y0+3] = a3*scale;
    }
    __syncthreads();

    {
        int warp = tid >> 5, lane = tid & 31;
        bool lastw = (wi == NW_ - 1);
        #pragma unroll
        for (int rr = 0; rr < 4; rr++) {
            int r = warp*4 + rr;
            float v = s[r][lane];
            float mx = v;
            #pragma unroll
            for (int o = 16; o > 0; o >>= 1) mx = fmaxf(mx, __shfl_xor_sync(0xffffffffu, mx, o));
            float e = expf(v - mx);
            float sm = e;
            #pragma unroll
            for (int o = 16; o > 0; o >>= 1) sm += __shfl_xor_sync(0xffffffffu, sm, o);
            v = e / sm;
            float bm = relt[(r - lane + WS_ - 1) * H_ + h];
            if (lastw && ((r < SHIFT_) != (lane < SHIFT_))) bm -= 100.0f;
            v += bm;
            mx = v;
            #pragma unroll
            for (int o = 16; o > 0; o >>= 1) mx = fmaxf(mx, __shfl_xor_sync(0xffffffffu, mx, o));
            e = expf(v - mx);
            sm = e;
            #pragma unroll
            for (int o = 16; o > 0; o >>= 1) sm += __shfl_xor_sync(0xffffffffu, sm, o);
            s[r][lane] = e / sm;
        }
    }
    __syncthreads();

    {
        int x  = tid >> 3;
        int j0 = (tid & 7) * 8;
        float acc[8] = {0.f,0.f,0.f,0.f,0.f,0.f,0.f,0.f};
        #pragma unroll
        for (int y = 0; y < WS_; y++) {
            float sv = s[x][y];
            const float* vp = &vs[y*D_ + j0];
            #pragma unroll
            for (int jj = 0; jj < 8; jj++)
                acc[jj] = fmaf(sv, vp[jj], acc[jj]);
        }
        float* op = out + (size_t)(win*WS_ + x) * C_ + h*D_ + j0;
        *(float4*)(op)   = make_float4(tf32r(acc[0]), tf32r(acc[1]), tf32r(acc[2]), tf32r(acc[3]));
        *(float4*)(op+4) = make_float4(tf32r(acc[4]), tf32r(acc[5]), tf32r(acc[6]), tf32r(acc[7]));
    }
}

// ==========================================================================
extern "C" void kernel_launch(void* const* d_in, const int* in_sizes, int n_in,
                              void* d_out, int out_size)
{
    const float* x      = (const float*)d_in[0];
    const float* w_qkv  = (const float*)d_in[1];
    const float* w_out  = (const float*)d_in[2];
    const float* b_out  = (const float*)d_in[3];
    const float* relt   = (const float*)d_in[4];
    const float* g1     = (const float*)d_in[5];
    const float* be1    = (const float*)d_in[6];
    const float* g2     = (const float*)d_in[7];
    const float* be2    = (const float*)d_in[8];
    const float* w_fc1  = (const float*)d_in[9];
    const float* b_fc1  = (const float*)d_in[10];
    const float* w_fc2  = (const float*)d_in[11];
    const float* b_fc2  = (const float*)d_in[12];
    float* out = (float*)d_out;

    float *hbuf, *qkvb, *obuf, *ybuf, *mlpb, *wr;
    cudaGetSymbolAddress((void**)&hbuf, g_h);
    cudaGetSymbolAddress((void**)&qkvb, g_qkv);
    cudaGetSymbolAddress((void**)&obuf, g_o);
    cudaGetSymbolAddress((void**)&ybuf, g_y);
    cudaGetSymbolAddress((void**)&mlpb, g_mlp);
    cudaGetSymbolAddress((void**)&wr,   g_wr);

    cudaFuncSetAttribute(tc_gemm<0>, cudaFuncAttributeMaxDynamicSharedMemorySize, SMEM_BYTES);
    cudaFuncSetAttribute(tc_gemm<1>, cudaFuncAttributeMaxDynamicSharedMemorySize, SMEM_BYTES);
    cudaFuncSetAttribute(tc_gemm<2>, cudaFuncAttributeMaxDynamicSharedMemorySize, SMEM_BYTES);
    cudaFuncSetAttribute(tc_gemm<3>, cudaFuncAttributeMaxDynamicSharedMemorySize, SMEM_BYTES);

    // 0) round weights to tf32 once per launch
    round_tf32_kernel<<<(786432/4 + 255)/256, 256>>>(w_qkv, wr + WR_QKV, 786432/4);
    round_tf32_kernel<<<(262144/4 + 255)/256, 256>>>(w_out, wr + WR_OUT, 262144/4);
    round_tf32_kernel<<<(1048576/4 + 255)/256, 256>>>(w_fc1, wr + WR_FC1, 1048576/4);
    round_tf32_kernel<<<(1048576/4 + 255)/256, 256>>>(w_fc2, wr + WR_FC2, 1048576/4);

    // 1) h = tf32(roll(LN1(x), -SHIFT))
    ln_roll_kernel<<<NTOK, 128>>>(x, g1, be1, hbuf, SHIFT_);

    // 2) qkv = h @ w_qkv^T
    tc_gemm<0><<<dim3(3*C_/BN, NTOK/BM), 256, SMEM_BYTES>>>(hbuf, wr + WR_QKV, nullptr, nullptr,
                                                            qkvb, C_, 3*C_);

    // 3) windowed attention -> tf32-rounded obuf
    attn_kernel<<<dim3(NWIN, H_), 256>>>(qkvb, relt, obuf);

    // 4+5) y = x + roll(obuf @ w_out^T + b_out, +SHIFT)   (fused epilogue)
    tc_gemm<3><<<dim3(C_/BN, NTOK/BM), 256, SMEM_BYTES>>>(obuf, wr + WR_OUT, b_out, x,
                                                          ybuf, C_, C_);

    // 6) h2 = tf32(LN2(y))
    ln_roll_kernel<<<NTOK, 128>>>(ybuf, g2, be2, hbuf, 0);

    // 7) mlp = tf32(gelu(h2 @ w_fc1^T + b_fc1))
    tc_gemm<1><<<dim3(MLP_/BN, NTOK/BM), 256, SMEM_BYTES>>>(hbuf, wr + WR_FC1, b_fc1, nullptr,
                                                            mlpb, C_, MLP_);

    // 8) out = y + mlp @ w_fc2^T + b_fc2
    tc_gemm<2><<<dim3(C_/BN, NTOK/BM), 256, SMEM_BYTES>>>(mlpb, wr + WR_FC2, b_fc2, ybuf,
                                                          out, MLP_, C_);
}